// round 5
// baseline (speedup 1.0000x reference)
#include <cuda_runtime.h>
#include <cuda_fp16.h>
#include <cstdint>

#define EE 256
#define HH 128
#define G4 512
#define BB 128
#define SS 1024
#define MM (SS*BB)
#define B512 (BB*G4)
#define NEGV -10000.0f

// scratch (static device memory)
__device__ float g_G[(size_t)2*SS*BB*G4];
__device__ float g_y1[(size_t)SS*BB*256];
__device__ float g_y2[(size_t)SS*BB*256];
__device__ float g_feats[(size_t)BB*SS*8];

__device__ __forceinline__ unsigned long long dup2(float a){
    unsigned long long r; asm("mov.b64 %0, {%1, %1};" : "=l"(r) : "f"(a)); return r;
}
__device__ __forceinline__ unsigned long long pk2(float a, float b){
    unsigned long long r; asm("mov.b64 %0, {%1, %2};" : "=l"(r) : "f"(a), "f"(b)); return r;
}
__device__ __forceinline__ void fma2(unsigned long long& d, unsigned long long a,
                                     unsigned long long b){
    asm("fma.rn.f32x2 %0, %1, %2, %0;" : "+l"(d) : "l"(a), "l"(b));
}
__device__ __forceinline__ float2 up2(unsigned long long v){
    float2 f; asm("mov.b64 {%0, %1}, %2;" : "=f"(f.x), "=f"(f.y) : "l"(v)); return f;
}
__device__ __forceinline__ float sigf(float x){
    return __fdividef(1.0f, 1.0f + __expf(-x));
}
__device__ __forceinline__ float tanhfast(float x){
    return __fdividef(2.0f, 1.0f + __expf(-2.0f * x)) - 1.0f;
}

// ---- K1/K3: G[d][t][b][512] = A[row] . W[n]^T + bih[n] + bhh[n] ----
__global__ __launch_bounds__(256) void gemm_proj(
    const float* __restrict__ Asrc, const int* __restrict__ tokens,
    const float* __restrict__ W, const float* __restrict__ bih,
    const float* __restrict__ bhh, float* __restrict__ G)
{
    __shared__ __align__(16) float As[16][64];
    __shared__ __align__(16) float Bs[16][64];
    __shared__ int rowidx[64];

    const int tid = threadIdx.x;
    const int n0 = blockIdx.x * 64;
    const int m0 = blockIdx.y * 64;

    if (tid < 64) rowidx[tid] = tokens ? tokens[m0 + tid] : (m0 + tid);
    __syncthreads();

    const int r = tid >> 2, c = tid & 3;
    const size_t arow = (size_t)rowidx[r] * 256;
    const float* wrow = W + (size_t)(n0 + r) * 256;
    const int ty = tid >> 4, tx = tid & 15;

    unsigned long long acc[4][2];
#pragma unroll
    for (int i = 0; i < 4; i++){ acc[i][0]=0ull; acc[i][1]=0ull; }

    for (int kc = 0; kc < 256; kc += 16){
        float4 av = *(const float4*)(Asrc + arow + kc + 4*c);
        float4 bv = *(const float4*)(wrow + kc + 4*c);
        As[4*c+0][r]=av.x; As[4*c+1][r]=av.y; As[4*c+2][r]=av.z; As[4*c+3][r]=av.w;
        Bs[4*c+0][r]=bv.x; Bs[4*c+1][r]=bv.y; Bs[4*c+2][r]=bv.z; Bs[4*c+3][r]=bv.w;
        __syncthreads();
#pragma unroll
        for (int kk = 0; kk < 16; kk++){
            float4 a = *(const float4*)&As[kk][ty*4];
            const unsigned long long* bp = (const unsigned long long*)&Bs[kk][tx*4];
            unsigned long long b0 = bp[0], b1 = bp[1];
            unsigned long long a0=dup2(a.x), a1=dup2(a.y), a2=dup2(a.z), a3=dup2(a.w);
            fma2(acc[0][0],a0,b0); fma2(acc[0][1],a0,b1);
            fma2(acc[1][0],a1,b0); fma2(acc[1][1],a1,b1);
            fma2(acc[2][0],a2,b0); fma2(acc[2][1],a2,b1);
            fma2(acc[3][0],a3,b0); fma2(acc[3][1],a3,b1);
        }
        __syncthreads();
    }

    const int d = n0 >> 9;
    const int j0 = (n0 & 511) + tx * 4;
    float bias[4];
#pragma unroll
    for (int q = 0; q < 4; q++){
        int n = n0 + tx*4 + q;
        bias[q] = bih[n] + bhh[n];
    }
#pragma unroll
    for (int i = 0; i < 4; i++){
        int m = m0 + ty*4 + i;
        float2 p0 = up2(acc[i][0]);
        float2 p1 = up2(acc[i][1]);
        float4 v = make_float4(p0.x+bias[0], p0.y+bias[1], p1.x+bias[2], p1.y+bias[3]);
        *(float4*)(G + ((size_t)d*MM + m)*G4 + j0) = v;
    }
}

// ---- K2/K4: recurrence. Block = (batch-pair, direction). Thread j owns gate row j. ----
__global__ __launch_bounds__(512, 1) void lstm_layer(
    const float* __restrict__ G, const float* __restrict__ whhL,
    const float* __restrict__ h0L, const float* __restrict__ c0L,
    float* __restrict__ Y)
{
    const int j = threadIdx.x;
    const int d = blockIdx.y;
    const int b0 = blockIdx.x * 2, b1 = b0 + 1;

    __shared__ __align__(16) float hcur[2][128];
    __shared__ float gbuf[2][512];

    const float* wr = whhL + ((size_t)d*G4 + j) * HH;
    half2 wh[64];
#pragma unroll
    for (int kk = 0; kk < 64; kk++)
        wh[kk] = __floats2half2_rn(wr[2*kk], wr[2*kk+1]);

    float cst0 = 0.f, cst1 = 0.f;
    if (j < 128){
        size_t base = (size_t)d * (BB*HH);
        hcur[0][j] = h0L[base + (size_t)b0*HH + j];
        hcur[1][j] = h0L[base + (size_t)b1*HH + j];
        cst0 = c0L[base + (size_t)b0*HH + j];
        cst1 = c0L[base + (size_t)b1*HH + j];
    }
    __syncthreads();

    const float* gp = G + (size_t)d*SS*BB*G4 + j;
    const size_t ob0 = (size_t)b0*G4, ob1 = ob0 + G4;

    int tfirst = d ? (SS-1) : 0;
    float gin0 = gp[(size_t)tfirst*B512 + ob0];
    float gin1 = gp[(size_t)tfirst*B512 + ob1];

    for (int s = 0; s < SS; s++){
        const int t = d ? (SS-1-s) : s;
        float ga = gin0, gb = gin1;
        if (s < SS-1){
            int tn = d ? (SS-2-s) : (s+1);
            size_t o = (size_t)tn*B512;
            gin0 = gp[o + ob0];
            gin1 = gp[o + ob1];
        }
        unsigned long long a0 = pk2(ga, 0.f);
        unsigned long long a1 = pk2(gb, 0.f);
#pragma unroll
        for (int kk = 0; kk < 64; kk++){
            float2 wf = __half22float2(wh[kk]);
            unsigned long long w2 = pk2(wf.x, wf.y);
            unsigned long long h0p = *(const unsigned long long*)&hcur[0][2*kk];
            unsigned long long h1p = *(const unsigned long long*)&hcur[1][2*kk];
            fma2(a0, w2, h0p);
            fma2(a1, w2, h1p);
        }
        float2 f0 = up2(a0), f1 = up2(a1);
        gbuf[0][j] = f0.x + f0.y;
        gbuf[1][j] = f1.x + f1.y;
        __syncthreads();

        if (j < 128){
            {
                float ig = sigf(gbuf[0][j]);
                float fg = sigf(gbuf[0][j+128]);
                float gg = tanhfast(gbuf[0][j+256]);
                float og = sigf(gbuf[0][j+384]);
                cst0 = fg*cst0 + ig*gg;
                float h = og * tanhfast(cst0);
                hcur[0][j] = h;
                Y[((size_t)t*BB + b0)*256 + d*128 + j] = h;
            }
            {
                float ig = sigf(gbuf[1][j]);
                float fg = sigf(gbuf[1][j+128]);
                float gg = tanhfast(gbuf[1][j+256]);
                float og = sigf(gbuf[1][j+384]);
                cst1 = fg*cst1 + ig*gg;
                float h = og * tanhfast(cst1);
                hcur[1][j] = h;
                Y[((size_t)t*BB + b1)*256 + d*128 + j] = h;
            }
        }
        __syncthreads();
    }
}

// ---- K5: feats[b][s][t] = y2[s*B+b,:] . w_out[t,:] + b_out[t], stride 8 ----
__global__ __launch_bounds__(256) void feats_kernel(
    const float* __restrict__ Y2, const float* __restrict__ wout,
    const float* __restrict__ bout, float* __restrict__ F)
{
    __shared__ float W[7][256];
    __shared__ float bo[7];
    const int tid = threadIdx.x;
    for (int i = tid; i < 7*256; i += 256) W[i>>8][i&255] = wout[i];
    if (tid < 7) bo[tid] = bout[tid];
    __syncthreads();

    const int warp = tid >> 5, lane = tid & 31;
    const size_t m = (size_t)blockIdx.x * 8 + warp;
    const float* yr = Y2 + m * 256;

    float acc[7] = {0,0,0,0,0,0,0};
#pragma unroll
    for (int i = 0; i < 8; i++){
        int k = lane + 32*i;
        float x = yr[k];
#pragma unroll
        for (int t = 0; t < 7; t++) acc[t] += x * W[t][k];
    }
#pragma unroll
    for (int t = 0; t < 7; t++)
        for (int off = 16; off; off >>= 1)
            acc[t] += __shfl_down_sync(0xffffffffu, acc[t], off);

    if (lane == 0){
        int s = (int)(m >> 7), b = (int)(m & 127);
        float* fo = F + ((size_t)b*SS + s)*8;
#pragma unroll
        for (int t = 0; t < 7; t++) fo[t] = acc[t] + bo[t];
    }
}

// ---- K6: Viterbi, one warp per batch element ----
__global__ __launch_bounds__(32) void viterbi_kernel(
    const float* __restrict__ F, const float* __restrict__ trans,
    float* __restrict__ out)
{
    __shared__ unsigned char bp[SS*8];
    const int b = blockIdx.x;
    const int lane = threadIdx.x;

    float tr[7];
#pragma unroll
    for (int p = 0; p < 7; p++) tr[p] = (lane < 7) ? trans[lane*7 + p] : 0.f;

    float fv = (lane == 5) ? 0.f : NEGV;   // START = 5
    const float* fb = F + (size_t)b*SS*8;

    for (int s = 0; s < SS; s++){
        float m = -3.4e38f;
        int arg = 0;
#pragma unroll
        for (int p = 0; p < 7; p++){
            float v = __shfl_sync(0xffffffffu, fv, p) + tr[p];
            if (v > m){ m = v; arg = p; }
        }
        if (lane < 7){
            fv = m + fb[s*8 + lane];
            bp[s*8 + lane] = (unsigned char)arg;
        }
    }
    __syncwarp();

    float term = fv + ((lane < 7) ? trans[6*7 + lane] : 0.f);  // STOP = 6
    if (lane >= 7) term = -3.4e38f;

    float bestv = -3.4e38f;
    int best = 0;
#pragma unroll
    for (int n = 0; n < 7; n++){
        float v = __shfl_sync(0xffffffffu, term, n);
        if (v > bestv){ bestv = v; best = n; }
    }

    if (lane == 0){
        out[(size_t)BB*SS + b] = bestv;
        float* po = out + (size_t)b*SS;
        int tag = best;
        for (int s = SS-1; s > 0; --s){
            po[s] = (float)tag;
            tag = bp[s*8 + tag];
        }
        po[0] = (float)tag;
    }
}

extern "C" void kernel_launch(void* const* d_in, const int* in_sizes, int n_in,
                              void* d_out, int out_size)
{
    const int*   sentence = (const int*)  d_in[0];
    const float* embed    = (const float*)d_in[1];
    const float* w_ih     = (const float*)d_in[2];
    const float* w_hh     = (const float*)d_in[3];
    const float* b_ih     = (const float*)d_in[4];
    const float* b_hh     = (const float*)d_in[5];
    const float* h0       = (const float*)d_in[6];
    const float* c0       = (const float*)d_in[7];
    const float* w_out    = (const float*)d_in[8];
    const float* b_out    = (const float*)d_in[9];
    const float* trans    = (const float*)d_in[10];
    float* out = (float*)d_out;

    float *G, *Y1, *Y2, *F;
    cudaGetSymbolAddress((void**)&G,  g_G);
    cudaGetSymbolAddress((void**)&Y1, g_y1);
    cudaGetSymbolAddress((void**)&Y2, g_y2);
    cudaGetSymbolAddress((void**)&F,  g_feats);

    dim3 ggrid(16, 2048);      // N-tiles x M-tiles (64x64)
    dim3 lgrid(64, 2);         // batch-pairs x directions

    // layer 1
    gemm_proj<<<ggrid, 256>>>(embed, sentence, w_ih, b_ih, b_hh, G);
    lstm_layer<<<lgrid, 512>>>(G, w_hh, h0, c0, Y1);
    // layer 2
    gemm_proj<<<ggrid, 256>>>(Y1, nullptr,
                              w_ih + (size_t)2*G4*EE,
                              b_ih + 2*G4, b_hh + 2*G4, G);
    lstm_layer<<<lgrid, 512>>>(G, w_hh + (size_t)2*G4*HH,
                               h0 + (size_t)2*BB*HH, c0 + (size_t)2*BB*HH, Y2);
    // feats + viterbi
    feats_kernel<<<MM/8, 256>>>(Y2, w_out, b_out, F);
    viterbi_kernel<<<BB, 32>>>(F, trans, out);
}

// round 6
// speedup vs baseline: 3.4617x; 3.4617x over previous
#include <cuda_runtime.h>
#include <cuda_fp16.h>
#include <cstdint>

#define EE 256
#define HH 128
#define G4 512
#define BB 128
#define SS 1024
#define MM (SS*BB)
#define NEGV -10000.0f

__device__ float  g_G[(size_t)2*MM*G4];
__device__ __half g_xh[(size_t)MM*256];
__device__ __half g_y1h[(size_t)MM*256];
__device__ __half g_y2h[(size_t)MM*256];
__device__ __half g_wh[(size_t)2*1024*256];
__device__ float  g_bs[2*1024];
__device__ float  g_feats[(size_t)BB*SS*8];

__device__ __forceinline__ unsigned h2u(float a, float b){
    __half2 h = __floats2half2_rn(a, b);
    return *(unsigned*)&h;
}
__device__ __forceinline__ void mma16816(float* c, const unsigned* a,
                                         unsigned b0, unsigned b1){
    asm volatile("mma.sync.aligned.m16n8k16.row.col.f32.f16.f16.f32 "
        "{%0,%1,%2,%3}, {%4,%5,%6,%7}, {%8,%9}, {%0,%1,%2,%3};"
        : "+f"(c[0]), "+f"(c[1]), "+f"(c[2]), "+f"(c[3])
        : "r"(a[0]), "r"(a[1]), "r"(a[2]), "r"(a[3]), "r"(b0), "r"(b1));
}
__device__ __forceinline__ void ldm4(unsigned* r, unsigned addr){
    asm volatile("ldmatrix.sync.aligned.m8n8.x4.shared.b16 {%0,%1,%2,%3}, [%4];"
        : "=r"(r[0]), "=r"(r[1]), "=r"(r[2]), "=r"(r[3]) : "r"(addr));
}
__device__ __forceinline__ float sigf(float x){
    return __fdividef(1.0f, 1.0f + __expf(-x));
}
__device__ __forceinline__ float tanhfast(float x){
    return __fdividef(2.0f, 1.0f + __expf(-2.0f * x)) - 1.0f;
}

// ---- prep: embedding gather -> fp16 ----
__global__ __launch_bounds__(256) void prep_x(
    const int* __restrict__ sent, const float* __restrict__ emb,
    __half* __restrict__ Xh)
{
    size_t i = (size_t)blockIdx.x * 256 + threadIdx.x;  // MM*32 threads
    int m = (int)(i >> 5);
    int c = ((int)i & 31) * 8;
    const float* src = emb + (size_t)sent[m]*256 + c;
    float4 v0 = *(const float4*)src;
    float4 v1 = *(const float4*)(src + 4);
    __half2* dst = (__half2*)(Xh + (size_t)m*256 + c);
    dst[0] = __floats2half2_rn(v0.x, v0.y);
    dst[1] = __floats2half2_rn(v0.z, v0.w);
    dst[2] = __floats2half2_rn(v1.x, v1.y);
    dst[3] = __floats2half2_rn(v1.z, v1.w);
}
__global__ __launch_bounds__(256) void prep_w(
    const float* __restrict__ wih, const float* __restrict__ bih,
    const float* __restrict__ bhh, __half* __restrict__ Wh, float* __restrict__ bs)
{
    size_t i = (size_t)blockIdx.x * 256 + threadIdx.x;  // 524288
    Wh[i] = __float2half(wih[i]);
    if (i < 2048) bs[i] = bih[i] + bhh[i];
}

// ---- HMMA GEMM: G[d][t*128+b][512] = X[m][256] . W[n][256]^T + bs[n] ----
// block: 128 M x 64 N, K=256 fully staged. 8 warps = 4(M) x 2(N).
#define XS_STR 264
__global__ __launch_bounds__(256) void gemm16(
    const __half* __restrict__ Xh, const __half* __restrict__ Wh,
    const float* __restrict__ bs, float* __restrict__ G)
{
    extern __shared__ __half sm[];
    __half* Xs = sm;                    // [128][264]
    __half* Ws = sm + 128*XS_STR;       // [64][264]
    const int tid = threadIdx.x;
    const int n0 = blockIdx.x * 64;
    const int m0 = blockIdx.y * 128;

    for (int it = 0; it < 16; it++){
        int idx = tid + 256*it, row = idx >> 5, c = idx & 31;
        *(uint4*)(Xs + row*XS_STR + c*8) =
            *(const uint4*)(Xh + (size_t)(m0+row)*256 + c*8);
    }
    for (int it = 0; it < 8; it++){
        int idx = tid + 256*it, row = idx >> 5, c = idx & 31;
        *(uint4*)(Ws + row*XS_STR + c*8) =
            *(const uint4*)(Wh + (size_t)(n0+row)*256 + c*8);
    }
    __syncthreads();

    const int w = tid >> 5, lane = tid & 31;
    const int wm = (w >> 1) * 32, wn = (w & 1) * 32;
    float acc[2][4][4];
#pragma unroll
    for (int i=0;i<2;i++) for (int j=0;j<4;j++) for (int k=0;k<4;k++) acc[i][j][k]=0.f;

    unsigned xbase = (unsigned)__cvta_generic_to_shared(Xs);
    unsigned wbase = (unsigned)__cvta_generic_to_shared(Ws);

    for (int kt = 0; kt < 16; kt++){
        unsigned a[2][4], b[2][4];
#pragma unroll
        for (int mt = 0; mt < 2; mt++){
            int row = wm + mt*16 + (lane & 15);
            int k = kt*16 + (lane >> 4)*8;
            ldm4(a[mt], xbase + (row*XS_STR + k)*2);
        }
#pragma unroll
        for (int nh = 0; nh < 2; nh++){
            int row = wn + nh*16 + ((lane>>4)&1)*8 + (lane & 7);
            int k = kt*16 + ((lane>>3)&1)*8;
            ldm4(b[nh], wbase + (row*XS_STR + k)*2);
        }
#pragma unroll
        for (int mt = 0; mt < 2; mt++){
            mma16816(acc[mt][0], a[mt], b[0][0], b[0][1]);
            mma16816(acc[mt][1], a[mt], b[0][2], b[0][3]);
            mma16816(acc[mt][2], a[mt], b[1][0], b[1][1]);
            mma16816(acc[mt][3], a[mt], b[1][2], b[1][3]);
        }
    }

    const int d = n0 >> 9;
    const int t = m0 >> 7;
#pragma unroll
    for (int mt = 0; mt < 2; mt++){
#pragma unroll
        for (int nt = 0; nt < 4; nt++){
            int g = n0 + wn + nt*8 + (lane & 3)*2;
            float b0 = bs[g], b1 = bs[g+1];
            int gl = g & 511;
            int bA = (m0 + wm + mt*16 + (lane>>2)) & 127;
            size_t o = ((size_t)d*MM + (size_t)t*128)*512 + gl;
            *(float2*)(G + o + (size_t)bA*512) =
                make_float2(acc[mt][nt][0]+b0, acc[mt][nt][1]+b1);
            *(float2*)(G + o + (size_t)(bA+8)*512) =
                make_float2(acc[mt][nt][2]+b0, acc[mt][nt][3]+b1);
        }
    }
}

// ---- LSTM recurrence: block = (8-batch group, dir). Whh in A-fragment regs. ----
__global__ __launch_bounds__(512, 1) void lstm_layer(
    const float* __restrict__ G, const float* __restrict__ whhL,
    const float* __restrict__ h0L, const float* __restrict__ c0L,
    __half* __restrict__ Yh)
{
    __shared__ __half hs[8][136];
    __shared__ float gbuf[512][10];

    const int tid = threadIdx.x;
    const int w = tid >> 5, lane = tid & 31;
    const int d = blockIdx.y;
    const int b0 = blockIdx.x * 8;

    // load Whh as A fragments: warp w owns gate rows [w*32, w*32+32)
    const float* wr = whhL + (size_t)d*G4*HH;
    unsigned wa[2][8][4];
#pragma unroll
    for (int mt = 0; mt < 2; mt++)
#pragma unroll
        for (int kt = 0; kt < 8; kt++)
#pragma unroll
            for (int r = 0; r < 4; r++){
                int row = w*32 + mt*16 + (lane>>2) + 8*(r & 1);
                int k = kt*16 + (lane&3)*2 + 8*(r >> 1);
                wa[mt][kt][r] = h2u(wr[(size_t)row*HH + k], wr[(size_t)row*HH + k + 1]);
            }

    // cell mapping for activation: thread owns (j, n0) and (j, n0+1)
    const int j = tid >> 2, n0c = (tid & 3) * 2;
    const size_t hb = (size_t)d*(BB*HH);
    float c0v = c0L[hb + (size_t)(b0+n0c)*HH + j];
    float c1v = c0L[hb + (size_t)(b0+n0c+1)*HH + j];
    hs[n0c][j]   = __float2half(h0L[hb + (size_t)(b0+n0c)*HH + j]);
    hs[n0c+1][j] = __float2half(h0L[hb + (size_t)(b0+n0c+1)*HH + j]);
    __syncthreads();

    const float* gbase = G + ((size_t)d*MM + b0 + n0c)*512 + j;
    int tf = d ? (SS-1) : 0;
    float gp0[4], gp1[4];
#pragma unroll
    for (int k = 0; k < 4; k++){
        gp0[k] = gbase[(size_t)tf*BB*512 + 128*k];
        gp1[k] = gbase[(size_t)tf*BB*512 + 512 + 128*k];
    }

    unsigned hsb = (unsigned)__cvta_generic_to_shared(&hs[0][0]);

    for (int s = 0; s < SS; s++){
        const int t = d ? (SS-1-s) : s;
        // mma: gates[512 x 8] = Whh * h
        float acc[2][4];
#pragma unroll
        for (int i=0;i<2;i++) for (int q=0;q<4;q++) acc[i][q]=0.f;
#pragma unroll
        for (int kt = 0; kt < 8; kt++){
            int koff = kt*16 + (lane&3)*2;
            unsigned off = (unsigned)((lane>>2)*136 + koff)*2;
            unsigned bf0, bf1;
            asm volatile("ld.shared.b32 %0, [%1];" : "=r"(bf0) : "r"(hsb + off));
            asm volatile("ld.shared.b32 %0, [%1];" : "=r"(bf1) : "r"(hsb + off + 16));
            mma16816(acc[0], wa[0][kt], bf0, bf1);
            mma16816(acc[1], wa[1][kt], bf0, bf1);
        }
#pragma unroll
        for (int mt = 0; mt < 2; mt++){
            int g = w*32 + mt*16 + (lane>>2), n = (lane&3)*2;
            *(float2*)&gbuf[g][n]   = make_float2(acc[mt][0], acc[mt][1]);
            *(float2*)&gbuf[g+8][n] = make_float2(acc[mt][2], acc[mt][3]);
        }
        __syncthreads();

        float gv0[4], gv1[4];
#pragma unroll
        for (int k = 0; k < 4; k++){
            gv0[k] = gbuf[j + 128*k][n0c]   + gp0[k];
            gv1[k] = gbuf[j + 128*k][n0c+1] + gp1[k];
        }
        if (s < SS-1){
            int tn = d ? (SS-2-s) : (s+1);
            size_t o = (size_t)tn*BB*512;
#pragma unroll
            for (int k = 0; k < 4; k++){
                gp0[k] = gbase[o + 128*k];
                gp1[k] = gbase[o + 512 + 128*k];
            }
        }
        {
            float ig = sigf(gv0[0]), fg = sigf(gv0[1]);
            float gg = tanhfast(gv0[2]), og = sigf(gv0[3]);
            c0v = fg*c0v + ig*gg;
            float h = og * tanhfast(c0v);
            hs[n0c][j] = __float2half(h);
            Yh[((size_t)t*BB + b0 + n0c)*256 + d*128 + j] = __float2half(h);
        }
        {
            float ig = sigf(gv1[0]), fg = sigf(gv1[1]);
            float gg = tanhfast(gv1[2]), og = sigf(gv1[3]);
            c1v = fg*c1v + ig*gg;
            float h = og * tanhfast(c1v);
            hs[n0c+1][j] = __float2half(h);
            Yh[((size_t)t*BB + b0 + n0c+1)*256 + d*128 + j] = __float2half(h);
        }
        __syncthreads();
    }
}

// ---- feats ----
__global__ __launch_bounds__(256) void feats_kernel(
    const __half* __restrict__ Y2, const float* __restrict__ wout,
    const float* __restrict__ bout, float* __restrict__ F)
{
    __shared__ float W[7][256];
    __shared__ float bo[7];
    const int tid = threadIdx.x;
    for (int i = tid; i < 7*256; i += 256) W[i>>8][i&255] = wout[i];
    if (tid < 7) bo[tid] = bout[tid];
    __syncthreads();
    const int warp = tid >> 5, lane = tid & 31;
    const size_t m = (size_t)blockIdx.x * 8 + warp;
    const __half* yr = Y2 + m * 256;
    float acc[7] = {0,0,0,0,0,0,0};
#pragma unroll
    for (int i = 0; i < 8; i++){
        int k = lane + 32*i;
        float x = __half2float(yr[k]);
#pragma unroll
        for (int t = 0; t < 7; t++) acc[t] += x * W[t][k];
    }
#pragma unroll
    for (int t = 0; t < 7; t++)
        for (int off = 16; off; off >>= 1)
            acc[t] += __shfl_down_sync(0xffffffffu, acc[t], off);
    if (lane == 0){
        int s = (int)(m >> 7), b = (int)(m & 127);
        float* fo = F + ((size_t)b*SS + s)*8;
#pragma unroll
        for (int t = 0; t < 7; t++) fo[t] = acc[t] + bo[t];
    }
}

// ---- Viterbi ----
__global__ __launch_bounds__(32) void viterbi_kernel(
    const float* __restrict__ F, const float* __restrict__ trans,
    float* __restrict__ out)
{
    __shared__ unsigned char bp[SS*8];
    const int b = blockIdx.x, lane = threadIdx.x;
    float tr[7];
#pragma unroll
    for (int p = 0; p < 7; p++) tr[p] = (lane < 7) ? trans[lane*7 + p] : 0.f;
    float fv = (lane == 5) ? 0.f : NEGV;
    const float* fb = F + (size_t)b*SS*8;
    for (int s = 0; s < SS; s++){
        float m = -3.4e38f; int arg = 0;
#pragma unroll
        for (int p = 0; p < 7; p++){
            float v = __shfl_sync(0xffffffffu, fv, p) + tr[p];
            if (v > m){ m = v; arg = p; }
        }
        if (lane < 7){
            fv = m + fb[s*8 + lane];
            bp[s*8 + lane] = (unsigned char)arg;
        }
    }
    __syncwarp();
    float term = fv + ((lane < 7) ? trans[6*7 + lane] : 0.f);
    if (lane >= 7) term = -3.4e38f;
    float bestv = -3.4e38f; int best = 0;
#pragma unroll
    for (int n = 0; n < 7; n++){
        float v = __shfl_sync(0xffffffffu, term, n);
        if (v > bestv){ bestv = v; best = n; }
    }
    if (lane == 0){
        out[(size_t)BB*SS + b] = bestv;
        float* po = out + (size_t)b*SS;
        int tag = best;
        for (int s = SS-1; s > 0; --s){ po[s] = (float)tag; tag = bp[s*8 + tag]; }
        po[0] = (float)tag;
    }
}

extern "C" void kernel_launch(void* const* d_in, const int* in_sizes, int n_in,
                              void* d_out, int out_size)
{
    const int*   sentence = (const int*)  d_in[0];
    const float* embed    = (const float*)d_in[1];
    const float* w_ih     = (const float*)d_in[2];
    const float* w_hh     = (const float*)d_in[3];
    const float* b_ih     = (const float*)d_in[4];
    const float* b_hh     = (const float*)d_in[5];
    const float* h0       = (const float*)d_in[6];
    const float* c0       = (const float*)d_in[7];
    const float* w_out    = (const float*)d_in[8];
    const float* b_out    = (const float*)d_in[9];
    const float* trans    = (const float*)d_in[10];
    float* out = (float*)d_out;

    float *G, *F, *BS;
    __half *Xh, *Y1h, *Y2h, *Wh;
    cudaGetSymbolAddress((void**)&G,   g_G);
    cudaGetSymbolAddress((void**)&F,   g_feats);
    cudaGetSymbolAddress((void**)&BS,  g_bs);
    cudaGetSymbolAddress((void**)&Xh,  g_xh);
    cudaGetSymbolAddress((void**)&Y1h, g_y1h);
    cudaGetSymbolAddress((void**)&Y2h, g_y2h);
    cudaGetSymbolAddress((void**)&Wh,  g_wh);

    const int gsmem = (128 + 64) * XS_STR * 2;
    cudaFuncSetAttribute(gemm16, cudaFuncAttributeMaxDynamicSharedMemorySize, gsmem);

    prep_x<<<MM*32/256, 256>>>(sentence, embed, Xh);
    prep_w<<<2048, 256>>>(w_ih, b_ih, b_hh, Wh, BS);

    dim3 ggrid(16, 1024);
    dim3 lgrid(16, 2);

    gemm16<<<ggrid, 256, gsmem>>>(Xh, Wh, BS, G);
    lstm_layer<<<lgrid, 512>>>(G, w_hh, h0, c0, Y1h);

    gemm16<<<ggrid, 256, gsmem>>>(Y1h, Wh + (size_t)1024*256, BS + 1024, G);
    lstm_layer<<<lgrid, 512>>>(G, w_hh + (size_t)1024*HH,
                               h0 + (size_t)2*BB*HH, c0 + (size_t)2*BB*HH, Y2h);

    feats_kernel<<<MM/8, 256>>>(Y2h, w_out, b_out, F);
    viterbi_kernel<<<BB, 32>>>(F, trans, out);
}

// round 8
// speedup vs baseline: 3.9668x; 1.1459x over previous
#include <cuda_runtime.h>
#include <cuda_fp16.h>
#include <cstdint>

#define EE 256
#define HH 128
#define G4 512
#define BB 128
#define SS 1024
#define MM (SS*BB)
#define NEGV -10000.0f

__device__ float  g_G[(size_t)2*MM*G4];
__device__ __half g_xh[(size_t)MM*256];
__device__ __half g_y1h[(size_t)MM*256];
__device__ __half g_y2h[(size_t)MM*256];
__device__ __half g_wh[(size_t)2*1024*256];
__device__ float  g_bs[2*1024];
__device__ float  g_feats[(size_t)BB*SS*8];

__device__ __forceinline__ unsigned h2u(float a, float b){
    __half2 h = __floats2half2_rn(a, b);
    return *(unsigned*)&h;
}
__device__ __forceinline__ void mma16816(float* c, const unsigned* a,
                                         unsigned b0, unsigned b1){
    asm volatile("mma.sync.aligned.m16n8k16.row.col.f32.f16.f16.f32 "
        "{%0,%1,%2,%3}, {%4,%5,%6,%7}, {%8,%9}, {%0,%1,%2,%3};"
        : "+f"(c[0]), "+f"(c[1]), "+f"(c[2]), "+f"(c[3])
        : "r"(a[0]), "r"(a[1]), "r"(a[2]), "r"(a[3]), "r"(b0), "r"(b1));
}
__device__ __forceinline__ void ldm4(unsigned* r, unsigned addr){
    asm volatile("ldmatrix.sync.aligned.m8n8.x4.shared.b16 {%0,%1,%2,%3}, [%4];"
        : "=r"(r[0]), "=r"(r[1]), "=r"(r[2]), "=r"(r[3]) : "r"(addr));
}
__device__ __forceinline__ float sigf(float x){
    return __fdividef(1.0f, 1.0f + __expf(-x));
}
__device__ __forceinline__ float tanhfast(float x){
    return __fdividef(2.0f, 1.0f + __expf(-2.0f * x)) - 1.0f;
}

// ---- prep ----
__global__ __launch_bounds__(256) void prep_x(
    const int* __restrict__ sent, const float* __restrict__ emb,
    __half* __restrict__ Xh)
{
    size_t i = (size_t)blockIdx.x * 256 + threadIdx.x;
    int m = (int)(i >> 5);
    int c = ((int)i & 31) * 8;
    const float* src = emb + (size_t)sent[m]*256 + c;
    float4 v0 = *(const float4*)src;
    float4 v1 = *(const float4*)(src + 4);
    __half2* dst = (__half2*)(Xh + (size_t)m*256 + c);
    dst[0] = __floats2half2_rn(v0.x, v0.y);
    dst[1] = __floats2half2_rn(v0.z, v0.w);
    dst[2] = __floats2half2_rn(v1.x, v1.y);
    dst[3] = __floats2half2_rn(v1.z, v1.w);
}
__global__ __launch_bounds__(256) void prep_w(
    const float* __restrict__ wih, const float* __restrict__ bih,
    const float* __restrict__ bhh, __half* __restrict__ Wh, float* __restrict__ bs)
{
    size_t i = (size_t)blockIdx.x * 256 + threadIdx.x;
    Wh[i] = __float2half(wih[i]);
    if (i < 2048) bs[i] = bih[i] + bhh[i];
}

// ---- HMMA GEMM 128x128 tile: G[d][t*128+b][512] = X.W^T + bs ----
#define XS_STR 264
__global__ __launch_bounds__(256, 1) void gemm16(
    const __half* __restrict__ Xh, const __half* __restrict__ Wh,
    const float* __restrict__ bs, float* __restrict__ G)
{
    extern __shared__ __half sm[];
    __half* Xs = sm;                    // [128][264]
    __half* Ws = sm + 128*XS_STR;       // [128][264]
    const int tid = threadIdx.x;
    const int n0 = blockIdx.x * 128;
    const int m0 = blockIdx.y * 128;

#pragma unroll
    for (int it = 0; it < 16; it++){
        int idx = tid + 256*it, row = idx >> 5, c = idx & 31;
        *(uint4*)(Xs + row*XS_STR + c*8) =
            *(const uint4*)(Xh + (size_t)(m0+row)*256 + c*8);
        *(uint4*)(Ws + row*XS_STR + c*8) =
            *(const uint4*)(Wh + (size_t)(n0+row)*256 + c*8);
    }
    __syncthreads();

    const int w = tid >> 5, lane = tid & 31;
    const int wm = (w >> 1) * 32, wn = (w & 1) * 64;
    float acc[2][8][4];
#pragma unroll
    for (int i=0;i<2;i++) for (int j=0;j<8;j++) for (int k=0;k<4;k++) acc[i][j][k]=0.f;

    unsigned xbase = (unsigned)__cvta_generic_to_shared(Xs);
    unsigned wbase = (unsigned)__cvta_generic_to_shared(Ws);

#pragma unroll
    for (int kt = 0; kt < 16; kt++){
        unsigned a[2][4], b[4][4];
#pragma unroll
        for (int mt = 0; mt < 2; mt++){
            int row = wm + mt*16 + (lane & 15);
            int k = kt*16 + (lane >> 4)*8;
            ldm4(a[mt], xbase + (row*XS_STR + k)*2);
        }
#pragma unroll
        for (int nh = 0; nh < 4; nh++){
            int row = wn + nh*16 + ((lane>>4)&1)*8 + (lane & 7);
            int k = kt*16 + ((lane>>3)&1)*8;
            ldm4(b[nh], wbase + (row*XS_STR + k)*2);
        }
#pragma unroll
        for (int mt = 0; mt < 2; mt++)
#pragma unroll
            for (int nh = 0; nh < 4; nh++){
                mma16816(acc[mt][nh*2],   a[mt], b[nh][0], b[nh][1]);
                mma16816(acc[mt][nh*2+1], a[mt], b[nh][2], b[nh][3]);
            }
    }

    const int d = n0 >> 9;
    const int t = m0 >> 7;
#pragma unroll
    for (int mt = 0; mt < 2; mt++){
#pragma unroll
        for (int nt = 0; nt < 8; nt++){
            int g = n0 + wn + nt*8 + (lane & 3)*2;
            float b0 = bs[g], b1 = bs[g+1];
            int gl = g & 511;
            int bA = (m0 + wm + mt*16 + (lane>>2)) & 127;
            size_t o = ((size_t)d*MM + (size_t)t*128)*512 + gl;
            *(float2*)(G + o + (size_t)bA*512) =
                make_float2(acc[mt][nt][0]+b0, acc[mt][nt][1]+b1);
            *(float2*)(G + o + (size_t)(bA+8)*512) =
                make_float2(acc[mt][nt][2]+b0, acc[mt][nt][3]+b1);
        }
    }
}

// ---- LSTM recurrence: block = (2-batch group, dir), 128 blocks ----
__global__ __launch_bounds__(512, 1) void lstm_layer(
    const float* __restrict__ G, const float* __restrict__ whhL,
    const float* __restrict__ h0L, const float* __restrict__ c0L,
    __half* __restrict__ Yh)
{
    __shared__ __half hs[8][136];
    __shared__ float gbuf[2][512];

    const int tid = threadIdx.x;
    const int w = tid >> 5, lane = tid & 31;
    const int d = blockIdx.y;
    const int b0 = blockIdx.x * 2;

    // Whh A fragments: warp w owns gate rows [w*32, w*32+32)
    const float* wr = whhL + (size_t)d*G4*HH;
    unsigned wa[2][8][4];
#pragma unroll
    for (int mt = 0; mt < 2; mt++)
#pragma unroll
        for (int kt = 0; kt < 8; kt++)
#pragma unroll
            for (int r = 0; r < 4; r++){
                int row = w*32 + mt*16 + (lane>>2) + 8*(r & 1);
                int k = kt*16 + (lane&3)*2 + 8*(r >> 1);
                wa[mt][kt][r] = h2u(wr[(size_t)row*HH + k], wr[(size_t)row*HH + k + 1]);
            }

    // zero hs, THEN sync, THEN write initial h (fixes R7 init race)
    for (int i = tid; i < 8*136; i += 512) (&hs[0][0])[i] = __float2half(0.f);
    __syncthreads();

    const int j = tid & 127, bl = (tid >> 7) & 1;   // valid for tid<256
    const size_t hb = (size_t)d*(BB*HH);
    float cv = 0.f;
    if (tid < 256){
        cv = c0L[hb + (size_t)(b0+bl)*HH + j];
        hs[bl][j] = __float2half(h0L[hb + (size_t)(b0+bl)*HH + j]);
    }
    __syncthreads();

    const float* gbase = G + ((size_t)d*MM + b0 + bl)*512 + j;
    int tf = d ? (SS-1) : 0;
    float gp[4];
    if (tid < 256){
#pragma unroll
        for (int k = 0; k < 4; k++)
            gp[k] = gbase[(size_t)tf*BB*512 + 128*k];
    }

    unsigned hsb = (unsigned)__cvta_generic_to_shared(&hs[0][0]);

    for (int s = 0; s < SS; s++){
        const int t = d ? (SS-1-s) : s;
        float acc[2][4];
#pragma unroll
        for (int i=0;i<2;i++) for (int q=0;q<4;q++) acc[i][q]=0.f;
#pragma unroll
        for (int kt = 0; kt < 8; kt++){
            unsigned off = (unsigned)((lane>>2)*136 + kt*16 + (lane&3)*2)*2;
            unsigned bf0, bf1;
            asm volatile("ld.shared.b32 %0, [%1];" : "=r"(bf0) : "r"(hsb + off));
            asm volatile("ld.shared.b32 %0, [%1];" : "=r"(bf1) : "r"(hsb + off + 16));
            mma16816(acc[0], wa[0][kt], bf0, bf1);
            mma16816(acc[1], wa[1][kt], bf0, bf1);
        }
        if ((lane & 3) == 0){
#pragma unroll
            for (int mt = 0; mt < 2; mt++){
                int g = w*32 + mt*16 + (lane>>2);
                gbuf[0][g]   = acc[mt][0];
                gbuf[1][g]   = acc[mt][1];
                gbuf[0][g+8] = acc[mt][2];
                gbuf[1][g+8] = acc[mt][3];
            }
        }
        __syncthreads();

        if (tid < 256){
            float g0 = gbuf[bl][j]       + gp[0];
            float g1 = gbuf[bl][j + 128] + gp[1];
            float g2 = gbuf[bl][j + 256] + gp[2];
            float g3 = gbuf[bl][j + 384] + gp[3];
            if (s < SS-1){
                int tn = d ? (SS-2-s) : (s+1);
                size_t o = (size_t)tn*BB*512;
#pragma unroll
                for (int k = 0; k < 4; k++) gp[k] = gbase[o + 128*k];
            }
            float ig = sigf(g0), fg = sigf(g1);
            float gg = tanhfast(g2), og = sigf(g3);
            cv = fg*cv + ig*gg;
            float h = og * tanhfast(cv);
            hs[bl][j] = __float2half(h);
            Yh[((size_t)t*BB + b0 + bl)*256 + d*128 + j] = __float2half(h);
        }
        __syncthreads();
    }
}

// ---- feats ----
__global__ __launch_bounds__(256) void feats_kernel(
    const __half* __restrict__ Y2, const float* __restrict__ wout,
    const float* __restrict__ bout, float* __restrict__ F)
{
    __shared__ float W[7][256];
    __shared__ float bo[7];
    const int tid = threadIdx.x;
    for (int i = tid; i < 7*256; i += 256) W[i>>8][i&255] = wout[i];
    if (tid < 7) bo[tid] = bout[tid];
    __syncthreads();
    const int warp = tid >> 5, lane = tid & 31;
    const size_t m = (size_t)blockIdx.x * 8 + warp;
    const __half* yr = Y2 + m * 256;
    float acc[7] = {0,0,0,0,0,0,0};
#pragma unroll
    for (int i = 0; i < 8; i++){
        int k = lane + 32*i;
        float x = __half2float(yr[k]);
#pragma unroll
        for (int t = 0; t < 7; t++) acc[t] += x * W[t][k];
    }
#pragma unroll
    for (int t = 0; t < 7; t++)
        for (int off = 16; off; off >>= 1)
            acc[t] += __shfl_down_sync(0xffffffffu, acc[t], off);
    if (lane == 0){
        int s = (int)(m >> 7), b = (int)(m & 127);
        float* fo = F + ((size_t)b*SS + s)*8;
#pragma unroll
        for (int t = 0; t < 7; t++) fo[t] = acc[t] + bo[t];
    }
}

// ---- Viterbi ----
__global__ __launch_bounds__(32) void viterbi_kernel(
    const float* __restrict__ F, const float* __restrict__ trans,
    float* __restrict__ out)
{
    __shared__ unsigned char bp[SS*8];
    const int b = blockIdx.x, lane = threadIdx.x;
    float tr[7];
#pragma unroll
    for (int p = 0; p < 7; p++) tr[p] = (lane < 7) ? trans[lane*7 + p] : 0.f;
    float fv = (lane == 5) ? 0.f : NEGV;
    const float* fb = F + (size_t)b*SS*8;
    for (int s = 0; s < SS; s++){
        float m = -3.4e38f; int arg = 0;
#pragma unroll
        for (int p = 0; p < 7; p++){
            float v = __shfl_sync(0xffffffffu, fv, p) + tr[p];
            if (v > m){ m = v; arg = p; }
        }
        if (lane < 7){
            fv = m + fb[s*8 + lane];
            bp[s*8 + lane] = (unsigned char)arg;
        }
    }
    __syncwarp();
    float term = fv + ((lane < 7) ? trans[6*7 + lane] : 0.f);
    if (lane >= 7) term = -3.4e38f;
    float bestv = -3.4e38f; int best = 0;
#pragma unroll
    for (int n = 0; n < 7; n++){
        float v = __shfl_sync(0xffffffffu, term, n);
        if (v > bestv){ bestv = v; best = n; }
    }
    if (lane == 0){
        out[(size_t)BB*SS + b] = bestv;
        float* po = out + (size_t)b*SS;
        int tag = best;
        for (int s = SS-1; s > 0; --s){ po[s] = (float)tag; tag = bp[s*8 + tag]; }
        po[0] = (float)tag;
    }
}

extern "C" void kernel_launch(void* const* d_in, const int* in_sizes, int n_in,
                              void* d_out, int out_size)
{
    const int*   sentence = (const int*)  d_in[0];
    const float* embed    = (const float*)d_in[1];
    const float* w_ih     = (const float*)d_in[2];
    const float* w_hh     = (const float*)d_in[3];
    const float* b_ih     = (const float*)d_in[4];
    const float* b_hh     = (const float*)d_in[5];
    const float* h0       = (const float*)d_in[6];
    const float* c0       = (const float*)d_in[7];
    const float* w_out    = (const float*)d_in[8];
    const float* b_out    = (const float*)d_in[9];
    const float* trans    = (const float*)d_in[10];
    float* out = (float*)d_out;

    float *G, *F, *BS;
    __half *Xh, *Y1h, *Y2h, *Wh;
    cudaGetSymbolAddress((void**)&G,   g_G);
    cudaGetSymbolAddress((void**)&F,   g_feats);
    cudaGetSymbolAddress((void**)&BS,  g_bs);
    cudaGetSymbolAddress((void**)&Xh,  g_xh);
    cudaGetSymbolAddress((void**)&Y1h, g_y1h);
    cudaGetSymbolAddress((void**)&Y2h, g_y2h);
    cudaGetSymbolAddress((void**)&Wh,  g_wh);

    const int gsmem = (128 + 128) * XS_STR * 2;
    cudaFuncSetAttribute(gemm16, cudaFuncAttributeMaxDynamicSharedMemorySize, gsmem);

    prep_x<<<MM*32/256, 256>>>(sentence, embed, Xh);
    prep_w<<<2048, 256>>>(w_ih, b_ih, b_hh, Wh, BS);

    dim3 ggrid(8, 1024);
    dim3 lgrid(64, 2);

    gemm16<<<ggrid, 256, gsmem>>>(Xh, Wh, BS, G);
    lstm_layer<<<lgrid, 512>>>(G, w_hh, h0, c0, Y1h);

    gemm16<<<ggrid, 256, gsmem>>>(Y1h, Wh + (size_t)1024*256, BS + 1024, G);
    lstm_layer<<<lgrid, 512>>>(G, w_hh + (size_t)1024*HH,
                               h0 + (size_t)2*BB*HH, c0 + (size_t)2*BB*HH, Y2h);

    feats_kernel<<<MM/8, 256>>>(Y2h, w_out, b_out, F);
    viterbi_kernel<<<BB, 32>>>(F, trans, out);
}

// round 9
// speedup vs baseline: 4.9388x; 1.2450x over previous
#include <cuda_runtime.h>
#include <cuda_fp16.h>
#include <cstdint>

#define EE 256
#define HH 128
#define G4 512
#define BB 128
#define SS 1024
#define MM (SS*BB)
#define NEGV -10000.0f

__device__ float  g_G[(size_t)2*MM*G4];
__device__ __half g_xh[(size_t)MM*256];
__device__ __half g_y1h[(size_t)MM*256];
__device__ __half g_y2h[(size_t)MM*256];
__device__ __half g_wh[(size_t)2*1024*256];
__device__ float  g_bs[2*1024];
__device__ float  g_feats[(size_t)BB*SS*8];

__device__ __forceinline__ unsigned h2u(float a, float b){
    __half2 h = __floats2half2_rn(a, b);
    return *(unsigned*)&h;
}
__device__ __forceinline__ void mma16816(float* c, const unsigned* a,
                                         unsigned b0, unsigned b1){
    asm volatile("mma.sync.aligned.m16n8k16.row.col.f32.f16.f16.f32 "
        "{%0,%1,%2,%3}, {%4,%5,%6,%7}, {%8,%9}, {%0,%1,%2,%3};"
        : "+f"(c[0]), "+f"(c[1]), "+f"(c[2]), "+f"(c[3])
        : "r"(a[0]), "r"(a[1]), "r"(a[2]), "r"(a[3]), "r"(b0), "r"(b1));
}
__device__ __forceinline__ void ldm4(unsigned* r, unsigned addr){
    asm volatile("ldmatrix.sync.aligned.m8n8.x4.shared.b16 {%0,%1,%2,%3}, [%4];"
        : "=r"(r[0]), "=r"(r[1]), "=r"(r[2]), "=r"(r[3]) : "r"(addr));
}
__device__ __forceinline__ float sigf(float x){
    return __fdividef(1.0f, 1.0f + __expf(-x));
}
__device__ __forceinline__ float tanhfast(float x){
    return __fdividef(2.0f, 1.0f + __expf(-2.0f * x)) - 1.0f;
}

// ---- prep ----
__global__ __launch_bounds__(256) void prep_x(
    const int* __restrict__ sent, const float* __restrict__ emb,
    __half* __restrict__ Xh)
{
    size_t i = (size_t)blockIdx.x * 256 + threadIdx.x;
    int m = (int)(i >> 5);
    int c = ((int)i & 31) * 8;
    const float* src = emb + (size_t)sent[m]*256 + c;
    float4 v0 = *(const float4*)src;
    float4 v1 = *(const float4*)(src + 4);
    __half2* dst = (__half2*)(Xh + (size_t)m*256 + c);
    dst[0] = __floats2half2_rn(v0.x, v0.y);
    dst[1] = __floats2half2_rn(v0.z, v0.w);
    dst[2] = __floats2half2_rn(v1.x, v1.y);
    dst[3] = __floats2half2_rn(v1.z, v1.w);
}
__global__ __launch_bounds__(256) void prep_w(
    const float* __restrict__ wih, const float* __restrict__ bih,
    const float* __restrict__ bhh, __half* __restrict__ Wh, float* __restrict__ bs)
{
    size_t i = (size_t)blockIdx.x * 256 + threadIdx.x;
    Wh[i] = __float2half(wih[i]);
    if (i < 2048) bs[i] = bih[i] + bhh[i];
}

// ---- HMMA GEMM 128x128 tile: G[d][t*128+b][512] = X.W^T + bs ----
#define XS_STR 264
__global__ __launch_bounds__(256, 1) void gemm16(
    const __half* __restrict__ Xh, const __half* __restrict__ Wh,
    const float* __restrict__ bs, float* __restrict__ G)
{
    extern __shared__ __half sm[];
    __half* Xs = sm;                    // [128][264]
    __half* Ws = sm + 128*XS_STR;       // [128][264]
    const int tid = threadIdx.x;
    const int n0 = blockIdx.x * 128;
    const int m0 = blockIdx.y * 128;

#pragma unroll
    for (int it = 0; it < 16; it++){
        int idx = tid + 256*it, row = idx >> 5, c = idx & 31;
        *(uint4*)(Xs + row*XS_STR + c*8) =
            *(const uint4*)(Xh + (size_t)(m0+row)*256 + c*8);
        *(uint4*)(Ws + row*XS_STR + c*8) =
            *(const uint4*)(Wh + (size_t)(n0+row)*256 + c*8);
    }
    __syncthreads();

    const int w = tid >> 5, lane = tid & 31;
    const int wm = (w >> 1) * 32, wn = (w & 1) * 64;
    float acc[2][8][4];
#pragma unroll
    for (int i=0;i<2;i++) for (int j=0;j<8;j++) for (int k=0;k<4;k++) acc[i][j][k]=0.f;

    unsigned xbase = (unsigned)__cvta_generic_to_shared(Xs);
    unsigned wbase = (unsigned)__cvta_generic_to_shared(Ws);

#pragma unroll
    for (int kt = 0; kt < 16; kt++){
        unsigned a[2][4], b[4][4];
#pragma unroll
        for (int mt = 0; mt < 2; mt++){
            int row = wm + mt*16 + (lane & 15);
            int k = kt*16 + (lane >> 4)*8;
            ldm4(a[mt], xbase + (row*XS_STR + k)*2);
        }
#pragma unroll
        for (int nh = 0; nh < 4; nh++){
            int row = wn + nh*16 + ((lane>>4)&1)*8 + (lane & 7);
            int k = kt*16 + ((lane>>3)&1)*8;
            ldm4(b[nh], wbase + (row*XS_STR + k)*2);
        }
#pragma unroll
        for (int mt = 0; mt < 2; mt++)
#pragma unroll
            for (int nh = 0; nh < 4; nh++){
                mma16816(acc[mt][nh*2],   a[mt], b[nh][0], b[nh][1]);
                mma16816(acc[mt][nh*2+1], a[mt], b[nh][2], b[nh][3]);
            }
    }

    const int d = n0 >> 9;
    const int t = m0 >> 7;
#pragma unroll
    for (int mt = 0; mt < 2; mt++){
#pragma unroll
        for (int nt = 0; nt < 8; nt++){
            int g = n0 + wn + nt*8 + (lane & 3)*2;
            float b0 = bs[g], b1 = bs[g+1];
            int gl = g & 511;
            int bA = (m0 + wm + mt*16 + (lane>>2)) & 127;
            size_t o = ((size_t)d*MM + (size_t)t*128)*512 + gl;
            *(float2*)(G + o + (size_t)bA*512) =
                make_float2(acc[mt][nt][0]+b0, acc[mt][nt][1]+b1);
            *(float2*)(G + o + (size_t)(bA+8)*512) =
                make_float2(acc[mt][nt][2]+b0, acc[mt][nt][3]+b1);
        }
    }
}

// ---- LSTM recurrence v2: block = (4-batch group, dir), 64 blocks.
// Warp w owns all 4 gates of cells [8w, 8w+8) (gate-permuted A fragments).
// Batch c lives at mma N-column 2c -> every lane holds exactly one
// (cell, batch) unit after the mma; activation is lane-local.
// Double-buffered h in smem -> ONE barrier per step. ----
__global__ __launch_bounds__(512, 1) void lstm_layer(
    const float* __restrict__ G, const float* __restrict__ whhL,
    const float* __restrict__ h0L, const float* __restrict__ c0L,
    __half* __restrict__ Yh)
{
    __shared__ __half hs[2][8][136];

    const int tid = threadIdx.x;
    const int w = tid >> 5, lane = tid & 31;
    const int d = blockIdx.y;
    const int b0 = blockIdx.x * 4;

    // Whh A fragments, permuted: fragment row grow -> Whh row gate*128 + cell
    const float* wr = whhL + (size_t)d*G4*HH;
    unsigned wa[2][8][4];
#pragma unroll
    for (int mt = 0; mt < 2; mt++)
#pragma unroll
        for (int kt = 0; kt < 8; kt++)
#pragma unroll
            for (int r = 0; r < 4; r++){
                int grow = mt*16 + (lane>>2) + 8*(r & 1);       // 0..31
                int row = (grow >> 3)*128 + w*8 + (grow & 7);   // gate*128 + cell
                int k = kt*16 + (lane&3)*2 + 8*(r >> 1);
                wa[mt][kt][r] = h2u(wr[(size_t)row*HH + k], wr[(size_t)row*HH + k + 1]);
            }

    // zero both h buffers, then init h0/c0 (one unit per lane)
    for (int i = tid; i < 2*8*136; i += 512) (&hs[0][0][0])[i] = __float2half(0.f);
    __syncthreads();

    const int q = lane >> 2, c = lane & 3;
    const int cell = w*8 + q;
    const size_t hb = (size_t)d*(BB*HH);
    float cv = c0L[hb + (size_t)(b0+c)*HH + cell];
    hs[0][2*c][cell] = __float2half(h0L[hb + (size_t)(b0+c)*HH + cell]);
    __syncthreads();

    // per-lane G pointer: gp[k] = G[(d*MM + t*128 + b0+c)*512 + k*128 + cell]
    const float* gbase = G + ((size_t)d*MM + b0 + c)*512 + cell;
    int tf = d ? (SS-1) : 0;
    float gp[4];
#pragma unroll
    for (int k = 0; k < 4; k++)
        gp[k] = gbase[(size_t)tf*BB*512 + 128*k];

    unsigned hsb0 = (unsigned)__cvta_generic_to_shared(&hs[0][0][0]);
    const unsigned boff = ((lane>>2)*136 + (lane&3)*2)*2;

    for (int s = 0; s < SS; s++){
        const int t = d ? (SS-1-s) : s;
        const int p = s & 1;
        unsigned hsb = hsb0 + (unsigned)(p * 8*136*2);

        float acc[2][4];
#pragma unroll
        for (int i=0;i<2;i++) for (int z=0;z<4;z++) acc[i][z]=0.f;
#pragma unroll
        for (int kt = 0; kt < 8; kt++){
            unsigned off = hsb + boff + kt*32;
            unsigned bf0, bf1;
            asm volatile("ld.shared.b32 %0, [%1];" : "=r"(bf0) : "r"(off));
            asm volatile("ld.shared.b32 %0, [%1];" : "=r"(bf1) : "r"(off + 16));
            mma16816(acc[0], wa[0][kt], bf0, bf1);
            mma16816(acc[1], wa[1][kt], bf0, bf1);
        }

        // lane-local gates: i=acc[0][0], f=acc[0][2], g=acc[1][0], o=acc[1][2]
        float gi = acc[0][0] + gp[0];
        float gf = acc[0][2] + gp[1];
        float gg = acc[1][0] + gp[2];
        float go = acc[1][2] + gp[3];

        if (s < SS-1){
            int tn = d ? (SS-2-s) : (s+1);
            size_t o = (size_t)tn*BB*512;
#pragma unroll
            for (int k = 0; k < 4; k++) gp[k] = gbase[o + 128*k];
        }

        float ig = sigf(gi), fg = sigf(gf);
        float g2 = tanhfast(gg), og = sigf(go);
        cv = fg*cv + ig*g2;
        float h = og * tanhfast(cv);

        hs[1-p][2*c][cell] = __float2half(h);
        Yh[((size_t)t*BB + b0 + c)*256 + d*128 + cell] = __float2half(h);
        __syncthreads();
    }
}

// ---- feats ----
__global__ __launch_bounds__(256) void feats_kernel(
    const __half* __restrict__ Y2, const float* __restrict__ wout,
    const float* __restrict__ bout, float* __restrict__ F)
{
    __shared__ float W[7][256];
    __shared__ float bo[7];
    const int tid = threadIdx.x;
    for (int i = tid; i < 7*256; i += 256) W[i>>8][i&255] = wout[i];
    if (tid < 7) bo[tid] = bout[tid];
    __syncthreads();
    const int warp = tid >> 5, lane = tid & 31;
    const size_t m = (size_t)blockIdx.x * 8 + warp;
    const __half* yr = Y2 + m * 256;
    float acc[7] = {0,0,0,0,0,0,0};
#pragma unroll
    for (int i = 0; i < 8; i++){
        int k = lane + 32*i;
        float x = __half2float(yr[k]);
#pragma unroll
        for (int t = 0; t < 7; t++) acc[t] += x * W[t][k];
    }
#pragma unroll
    for (int t = 0; t < 7; t++)
        for (int off = 16; off; off >>= 1)
            acc[t] += __shfl_down_sync(0xffffffffu, acc[t], off);
    if (lane == 0){
        int s = (int)(m >> 7), b = (int)(m & 127);
        float* fo = F + ((size_t)b*SS + s)*8;
#pragma unroll
        for (int t = 0; t < 7; t++) fo[t] = acc[t] + bo[t];
    }
}

// ---- Viterbi ----
__global__ __launch_bounds__(32) void viterbi_kernel(
    const float* __restrict__ F, const float* __restrict__ trans,
    float* __restrict__ out)
{
    __shared__ unsigned char bp[SS*8];
    const int b = blockIdx.x, lane = threadIdx.x;
    float tr[7];
#pragma unroll
    for (int p = 0; p < 7; p++) tr[p] = (lane < 7) ? trans[lane*7 + p] : 0.f;
    float fv = (lane == 5) ? 0.f : NEGV;
    const float* fb = F + (size_t)b*SS*8;
    for (int s = 0; s < SS; s++){
        float m = -3.4e38f; int arg = 0;
#pragma unroll
        for (int p = 0; p < 7; p++){
            float v = __shfl_sync(0xffffffffu, fv, p) + tr[p];
            if (v > m){ m = v; arg = p; }
        }
        if (lane < 7){
            fv = m + fb[s*8 + lane];
            bp[s*8 + lane] = (unsigned char)arg;
        }
    }
    __syncwarp();
    float term = fv + ((lane < 7) ? trans[6*7 + lane] : 0.f);
    if (lane >= 7) term = -3.4e38f;
    float bestv = -3.4e38f; int best = 0;
#pragma unroll
    for (int n = 0; n < 7; n++){
        float v = __shfl_sync(0xffffffffu, term, n);
        if (v > bestv){ bestv = v; best = n; }
    }
    if (lane == 0){
        out[(size_t)BB*SS + b] = bestv;
        float* po = out + (size_t)b*SS;
        int tag = best;
        for (int s = SS-1; s > 0; --s){ po[s] = (float)tag; tag = bp[s*8 + tag]; }
        po[0] = (float)tag;
    }
}

extern "C" void kernel_launch(void* const* d_in, const int* in_sizes, int n_in,
                              void* d_out, int out_size)
{
    const int*   sentence = (const int*)  d_in[0];
    const float* embed    = (const float*)d_in[1];
    const float* w_ih     = (const float*)d_in[2];
    const float* w_hh     = (const float*)d_in[3];
    const float* b_ih     = (const float*)d_in[4];
    const float* b_hh     = (const float*)d_in[5];
    const float* h0       = (const float*)d_in[6];
    const float* c0       = (const float*)d_in[7];
    const float* w_out    = (const float*)d_in[8];
    const float* b_out    = (const float*)d_in[9];
    const float* trans    = (const float*)d_in[10];
    float* out = (float*)d_out;

    float *G, *F, *BS;
    __half *Xh, *Y1h, *Y2h, *Wh;
    cudaGetSymbolAddress((void**)&G,   g_G);
    cudaGetSymbolAddress((void**)&F,   g_feats);
    cudaGetSymbolAddress((void**)&BS,  g_bs);
    cudaGetSymbolAddress((void**)&Xh,  g_xh);
    cudaGetSymbolAddress((void**)&Y1h, g_y1h);
    cudaGetSymbolAddress((void**)&Y2h, g_y2h);
    cudaGetSymbolAddress((void**)&Wh,  g_wh);

    const int gsmem = (128 + 128) * XS_STR * 2;
    cudaFuncSetAttribute(gemm16, cudaFuncAttributeMaxDynamicSharedMemorySize, gsmem);

    prep_x<<<MM*32/256, 256>>>(sentence, embed, Xh);
    prep_w<<<2048, 256>>>(w_ih, b_ih, b_hh, Wh, BS);

    dim3 ggrid(8, 1024);
    dim3 lgrid(32, 2);

    gemm16<<<ggrid, 256, gsmem>>>(Xh, Wh, BS, G);
    lstm_layer<<<lgrid, 512>>>(G, w_hh, h0, c0, Y1h);

    gemm16<<<ggrid, 256, gsmem>>>(Y1h, Wh + (size_t)1024*256, BS + 1024, G);
    lstm_layer<<<lgrid, 512>>>(G, w_hh + (size_t)1024*HH,
                               h0 + (size_t)2*BB*HH, c0 + (size_t)2*BB*HH, Y2h);

    feats_kernel<<<MM/8, 256>>>(Y2h, w_out, b_out, F);
    viterbi_kernel<<<BB, 32>>>(F, trans, out);
}